// round 2
// baseline (speedup 1.0000x reference)
#include <cuda_runtime.h>
#include <math.h>

#define BATCH 32768
#define FEAT  40
#define DCOLS 496
#define NT    1000

__device__ float g_la[NT], g_l1ma[NT], g_lca[NT], g_l1mca[NT];
__device__ float g_cs_part[8][DCOLS];
__device__ float g_colsum[DCOLS];
__device__ float g_row_loss[BATCH];

__constant__ float c_lognc[5] = {0.69314718055994531f, 1.38629436111989062f,
                                 2.07944154167983593f, 2.77258872223978124f,
                                 3.46573590279972655f};
__constant__ int c_off[5] = {0, 2, 6, 14, 30};

#define CLOG (-69.07755278982137f)   // log(1e-30)

__device__ __forceinline__ float lae(float a, float b) {
    float mx = fmaxf(a, b);
    return mx + log1pf(expf(-fabsf(a - b)));
}

__device__ __forceinline__ float wred(float v) {
    #pragma unroll
    for (int o = 16; o; o >>= 1) v += __shfl_down_sync(0xffffffffu, v, o);
    return v;
}

// ---------------------------------------------------------------------------
// Diffusion schedule: beta = linspace(1e-4, 0.02, 1000); log_ca via double
// prefix-scan of log(alpha) (matches numpy float64 cumprod to <1e-11 rel).
// ---------------------------------------------------------------------------
__global__ void sched_kernel() {
    __shared__ double s[1024];
    int t = threadIdx.x;
    double la = 0.0;
    if (t < NT) {
        double beta = (t == NT - 1) ? 0.02 : (1e-4 + (double)t * ((0.02 - 1e-4) / 999.0));
        double alpha = 1.0 - beta;
        la = log(alpha);
        g_la[t]   = (float)la;
        g_l1ma[t] = (float)log(1.0 - alpha);
    }
    s[t] = la;
    __syncthreads();
    for (int off = 1; off < 1024; off <<= 1) {
        double v = (t >= off) ? s[t - off] : 0.0;
        __syncthreads();
        s[t] += v;
        __syncthreads();
    }
    if (t < NT) {
        double lc = s[t];
        g_lca[t]   = (float)lc;
        g_l1mca[t] = (float)log1p(-exp(lc));
    }
}

// ---------------------------------------------------------------------------
// colsum[j] = sum_d W[d][j], deterministic two-stage (no float atomics).
// ---------------------------------------------------------------------------
__global__ void cs_part_kernel(const float* __restrict__ W) {
    int j = blockIdx.x * 128 + threadIdx.x;
    int r0 = blockIdx.y * 62;
    if (j < DCOLS) {
        float s0 = 0.f, s1 = 0.f;
        #pragma unroll
        for (int d = 0; d < 62; d += 2) {
            s0 += W[(size_t)(r0 + d) * DCOLS + j];
            s1 += W[(size_t)(r0 + d + 1) * DCOLS + j];
        }
        g_cs_part[blockIdx.y][j] = s0 + s1;
    }
}

__global__ void cs_comb_kernel() {
    int j = blockIdx.x * 128 + threadIdx.x;
    if (j < DCOLS) {
        float s = 0.f;
        #pragma unroll
        for (int i = 0; i < 8; i++) s += g_cs_part[i][j];
        g_colsum[j] = s;
    }
}

// ---------------------------------------------------------------------------
// Main: one block per batch row, 128 threads; thread t owns columns 4t..4t+3.
// ---------------------------------------------------------------------------
__global__ __launch_bounds__(128) void ddpm_kernel(
    const int*   __restrict__ x0,
    const int*   __restrict__ tsteps,
    const float* __restrict__ uni,
    const float* __restrict__ W,
    const float* __restrict__ bias,
    const float* __restrict__ temb)
{
    const int b   = blockIdx.x;
    const int tid = threadIdx.x;

    __shared__ float sm[DCOLS];
    __shared__ int   s_col0[FEAT];
    __shared__ int   s_w[FEAT];
    __shared__ float s_lse[FEAT];
    __shared__ float s_lp0[FEAT], s_lpo[FEAT];
    __shared__ float s_q1w[FEAT], s_q1o[FEAT];
    __shared__ float s_lt[FEAT][3], s_elt[FEAT][3];   // class: 0=other,1=c0,2=w
    __shared__ float s_red[3][4];

    const int   t     = tsteps[b];
    const float lca   = g_lca[t],  l1mca  = g_l1mca[t];
    const float la    = g_la[t],   l1ma   = g_l1ma[t];
    const int   tm1   = (t > 0) ? t - 1 : 0;
    const float lca1  = g_lca[tm1], l1mca1 = g_l1mca[tm1];

    // per-feature constants + x0 columns
    if (tid < FEAT) {
        int f = tid, g = f / 5, k = f - 5 * g;
        int start = g * 62 + c_off[k];
        float lognc = c_lognc[k];
        s_col0[f] = start + x0[b * FEAT + f];
        s_lp0[f]  = lae(lca,        l1mca - lognc);   // q_prior at x0 col
        s_lpo[f]  = lae(CLOG + lca, l1mca - lognc);   // q_prior elsewhere
        s_q1w[f]  = lae(la,         l1ma - lognc);    // q_one_timestep at xt col
        s_q1o[f]  = lae(CLOG + la,  l1ma - lognc);
    }
    __syncthreads();

    const int  j0  = tid * 4;
    const bool act = (j0 < DCOLS);

    // -------- phase 1: z = gumbel + q_prior logits --------
    if (act) {
        float4 u4 = *reinterpret_cast<const float4*>(uni + (size_t)b * DCOLS + j0);
        const float* up = reinterpret_cast<const float*>(&u4);
        #pragma unroll
        for (int q = 0; q < 4; q++) {
            int j = j0 + q;
            int g = j / 62, o = j - 62 * g;
            int k = (o < 2) ? 0 : (o < 6) ? 1 : (o < 14) ? 2 : (o < 30) ? 3 : 4;
            int f = 5 * g + k;
            float gum = -logf(-logf(up[q] + 1e-30f) + 1e-30f);
            float lp  = (j == s_col0[f]) ? s_lp0[f] : s_lpo[f];
            sm[j] = gum + lp;
        }
    }
    __syncthreads();

    // per-segment argmax (first-max tie break, matches reference)
    if (tid < FEAT) {
        int f = tid, g = f / 5, k = f - 5 * g;
        int start = g * 62 + c_off[k], wdt = 2 << k;
        float best = -3.4e38f; int bi = start;
        for (int j = start; j < start + wdt; j++) {
            float v = sm[j];
            if (v > best) { best = v; bi = j; }
        }
        s_w[f] = bi;
    }
    __syncthreads();

    // -------- phase 2: gather-sum of 40 W rows; pred --------
    float pred[4] = {0, 0, 0, 0};
    if (act) {
        float ax = 0, ay = 0, az = 0, aw = 0;
        const float* Wb = W + j0;
        #pragma unroll 8
        for (int f = 0; f < FEAT; f++) {
            float4 v = *reinterpret_cast<const float4*>(Wb + (size_t)s_w[f] * DCOLS);
            ax += v.x; ay += v.y; az += v.z; aw += v.w;
        }
        float4 cs = *reinterpret_cast<const float4*>(g_colsum + j0);
        float4 bb = *reinterpret_cast<const float4*>(bias + j0);
        float4 te = *reinterpret_cast<const float4*>(temb + (size_t)t * DCOLS + j0);
        pred[0] = CLOG * (cs.x - ax) + bb.x + te.x;
        pred[1] = CLOG * (cs.y - ay) + bb.y + te.y;
        pred[2] = CLOG * (cs.z - az) + bb.z + te.z;
        pred[3] = CLOG * (cs.w - aw) + bb.w + te.w;
        sm[j0] = pred[0]; sm[j0+1] = pred[1]; sm[j0+2] = pred[2]; sm[j0+3] = pred[3];
    }
    __syncthreads();

    // lse(pred) per segment + closed-form TRUE posterior per class
    if (tid < FEAT) {
        int f = tid, g = f / 5, k = f - 5 * g;
        int start = g * 62 + c_off[k], wdt = 2 << k;
        float m = -3.4e38f;
        for (int j = start; j < start + wdt; j++) m = fmaxf(m, sm[j]);
        float s = 0.f;
        for (int j = start; j < start + wdt; j++) s += expf(sm[j] - m);
        s_lse[f] = m + logf(s);

        float lognc = c_lognc[k];
        int c0 = s_col0[f], w = s_w[f];
        float ev0 = (t == 0) ? 0.f  : lae(lca1,        l1mca1 - lognc);
        float evo = (t == 0) ? CLOG : lae(CLOG + lca1, l1mca1 - lognc);
        float q1w = s_q1w[f], q1o = s_q1o[f];
        float un_oo = evo + q1o;
        float lt0, lt1, lt2;
        if (c0 == w) {
            float un_b = ev0 + q1w;
            float mm = fmaxf(un_b, un_oo);
            float ss = expf(un_b - mm) + (float)(wdt - 1) * expf(un_oo - mm);
            float lse = mm + logf(ss);
            lt1 = un_b - lse; lt2 = lt1; lt0 = un_oo - lse;
        } else {
            float un_c0 = ev0 + q1o;
            float un_w  = evo + q1w;
            float mm = fmaxf(fmaxf(un_c0, un_w), un_oo);   // un_oo <= both, safe for wdt==2
            float ss = expf(un_c0 - mm) + expf(un_w - mm) + (float)(wdt - 2) * expf(un_oo - mm);
            float lse = mm + logf(ss);
            lt0 = un_oo - lse; lt1 = un_c0 - lse; lt2 = un_w - lse;
        }
        s_lt[f][0] = lt0; s_lt[f][1] = lt1; s_lt[f][2] = lt2;
        s_elt[f][0] = expf(lt0); s_elt[f][1] = expf(lt1); s_elt[f][2] = expf(lt2);
    }
    __syncthreads();

    // -------- phase 3: EST posterior (dense) --------
    float un_e[4] = {0, 0, 0, 0};
    if (act) {
        #pragma unroll
        for (int q = 0; q < 4; q++) {
            int j = j0 + q;
            int g = j / 62, o = j - 62 * g;
            int k = (o < 2) ? 0 : (o < 6) ? 1 : (o < 14) ? 2 : (o < 30) ? 3 : 4;
            int f = 5 * g + k;
            float lognc = c_lognc[k];
            float lh = pred[q] - s_lse[f];                       // log_x0_hat
            float q1 = (j == s_w[f]) ? s_q1w[f] : s_q1o[f];
            float ev = (t == 0) ? lh : lae(lh + lca1, l1mca1 - lognc);
            un_e[q] = ev + q1;
            sm[j] = un_e[q];
        }
    }
    __syncthreads();
    if (tid < FEAT) {
        int f = tid, g = f / 5, k = f - 5 * g;
        int start = g * 62 + c_off[k], wdt = 2 << k;
        float m = -3.4e38f;
        for (int j = start; j < start + wdt; j++) m = fmaxf(m, sm[j]);
        float s = 0.f;
        for (int j = start; j < start + wdt; j++) s += expf(sm[j] - m);
        s_lse[f] = m + logf(s);
    }
    __syncthreads();

    // -------- phase 4: losses --------
    float kl = 0.f, dec = 0.f, pr = 0.f;
    if (act) {
        #pragma unroll
        for (int q = 0; q < 4; q++) {
            int j = j0 + q;
            int g = j / 62, o = j - 62 * g;
            int k = (o < 2) ? 0 : (o < 6) ? 1 : (o < 14) ? 2 : (o < 30) ? 3 : 4;
            int f = 5 * g + k;
            float le = un_e[q] - s_lse[f];
            bool isc0 = (j == s_col0[f]);
            int cls = isc0 ? 1 : ((j == s_w[f]) ? 2 : 0);
            kl += s_elt[f][cls] * (s_lt[f][cls] - le);
            if (isc0) dec -= le;
        }
    }
    if (tid < FEAT) {   // kl_prior closed form per feature
        int k = tid % 5;
        float lognc = c_lognc[k];
        int wdt = 2 << k;
        float lcaT = g_lca[NT - 1], l1mcaT = g_l1mca[NT - 1];
        float lq0 = lae(lcaT,        l1mcaT - lognc);
        float lqo = lae(CLOG + lcaT, l1mcaT - lognc);
        pr = expf(lq0) * (lq0 + lognc) + (float)(wdt - 1) * (expf(lqo) * (lqo + lognc));
    }

    float rk = wred(kl), rd = wred(dec), rp = wred(pr);
    int wid = tid >> 5, lane = tid & 31;
    if (lane == 0) { s_red[0][wid] = rk; s_red[1][wid] = rd; s_red[2][wid] = rp; }
    __syncthreads();
    if (tid == 0) {
        float K  = s_red[0][0] + s_red[0][1] + s_red[0][2] + s_red[0][3];
        float Dn = s_red[1][0] + s_red[1][1] + s_red[1][2] + s_red[1][3];
        float P  = s_red[2][0] + s_red[2][1] + s_red[2][2] + s_red[2][3];
        float diff = (t == 0) ? Dn : K;
        g_row_loss[b] = diff * 1000.0f + P;
    }
}

__global__ void reduce_kernel(float* __restrict__ out) {
    __shared__ double sd[32];
    int tid = threadIdx.x;
    double s = 0.0;
    for (int i = tid; i < BATCH; i += 1024) s += (double)g_row_loss[i];
    #pragma unroll
    for (int o = 16; o; o >>= 1) s += __shfl_down_sync(0xffffffffu, s, o);
    if ((tid & 31) == 0) sd[tid >> 5] = s;
    __syncthreads();
    if (tid < 32) {
        double v = sd[tid];
        #pragma unroll
        for (int o = 16; o; o >>= 1) v += __shfl_down_sync(0xffffffffu, v, o);
        if (tid == 0) out[0] = (float)(v / (double)BATCH);
    }
}

extern "C" void kernel_launch(void* const* d_in, const int* in_sizes, int n_in,
                              void* d_out, int out_size)
{
    // Map inputs by element count (robust to ordering surprises).
    const int*   x0 = nullptr;  const int*   ts = nullptr;
    const float* un = nullptr;  const float* W  = nullptr;
    const float* bi = nullptr;  const float* te = nullptr;
    for (int i = 0; i < n_in; i++) {
        switch (in_sizes[i]) {
            case BATCH * FEAT:   x0 = (const int*)d_in[i];   break;
            case BATCH:          ts = (const int*)d_in[i];   break;
            case BATCH * DCOLS:  un = (const float*)d_in[i]; break;
            case DCOLS * DCOLS:  W  = (const float*)d_in[i]; break;
            case DCOLS:          bi = (const float*)d_in[i]; break;
            case NT * DCOLS:     te = (const float*)d_in[i]; break;
            default: break;
        }
    }
    float* out = (float*)d_out;

    sched_kernel<<<1, 1024>>>();
    dim3 gcs(4, 8);
    cs_part_kernel<<<gcs, 128>>>(W);
    cs_comb_kernel<<<4, 128>>>();
    ddpm_kernel<<<BATCH, 128>>>(x0, ts, un, W, bi, te);
    reduce_kernel<<<1, 1024>>>(out);
}

// round 3
// speedup vs baseline: 1.0771x; 1.0771x over previous
#include <cuda_runtime.h>
#include <math.h>

#define BATCH 32768
#define FEAT  40
#define DCOLS 496
#define NT    1000

__device__ float g_la[NT], g_l1ma[NT], g_lca[NT], g_l1mca[NT];
__device__ float g_cs_part[8][DCOLS];
__device__ float g_colsum[DCOLS];
__device__ float g_row_loss[BATCH];

__constant__ float c_lognc[5] = {0.69314718055994531f, 1.38629436111989062f,
                                 2.07944154167983593f, 2.77258872223978124f,
                                 3.46573590279972655f};
__constant__ int c_off[5] = {0, 2, 6, 14, 30};

#define CLOG (-69.07755278982137f)   // log(1e-30)

// precise (used only on 40 scanner threads where it is cheap)
__device__ __forceinline__ float lae(float a, float b) {
    float mx = fmaxf(a, b);
    return mx + log1pf(expf(-fabsf(a - b)));
}
// fast logaddexp for the dense per-column path
__device__ __forceinline__ float flae(float a, float b) {
    float mx = fmaxf(a, b);
    return mx + __logf(1.0f + __expf(-fabsf(a - b)));
}

__device__ __forceinline__ float wred(float v) {
    #pragma unroll
    for (int o = 16; o; o >>= 1) v += __shfl_down_sync(0xffffffffu, v, o);
    return v;
}

// ---------------------------------------------------------------------------
// Diffusion schedule in float (1e-3 tolerance makes float64 overkill):
// log_alpha = log1p(-beta); log_ca = prefix-sum; log_1m_ca = log(-expm1(lc)).
// ---------------------------------------------------------------------------
__global__ void sched_kernel() {
    __shared__ float s[1024];
    int t = threadIdx.x;
    float la = 0.0f;
    if (t < NT) {
        float beta = (t == NT - 1) ? 0.02f : (1e-4f + (float)t * ((0.02f - 1e-4f) / 999.0f));
        la = log1pf(-beta);
        g_la[t]   = la;
        g_l1ma[t] = logf(beta);
    }
    s[t] = la;
    __syncthreads();
    for (int off = 1; off < 1024; off <<= 1) {
        float v = (t >= off) ? s[t - off] : 0.0f;
        __syncthreads();
        s[t] += v;
        __syncthreads();
    }
    if (t < NT) {
        float lc = s[t];
        g_lca[t]   = lc;
        g_l1mca[t] = logf(-expm1f(lc));
    }
}

// ---------------------------------------------------------------------------
// colsum[j] = sum_d W[d][j], deterministic two-stage.
// ---------------------------------------------------------------------------
__global__ void cs_part_kernel(const float* __restrict__ W) {
    int j = blockIdx.x * 128 + threadIdx.x;
    int r0 = blockIdx.y * 62;
    if (j < DCOLS) {
        float s0 = 0.f, s1 = 0.f;
        #pragma unroll
        for (int d = 0; d < 62; d += 2) {
            s0 += W[(size_t)(r0 + d) * DCOLS + j];
            s1 += W[(size_t)(r0 + d + 1) * DCOLS + j];
        }
        g_cs_part[blockIdx.y][j] = s0 + s1;
    }
}

__global__ void cs_comb_kernel() {
    int j = blockIdx.x * 128 + threadIdx.x;
    if (j < DCOLS) {
        float s = 0.f;
        #pragma unroll
        for (int i = 0; i < 8; i++) s += g_cs_part[i][j];
        g_colsum[j] = s;
    }
}

// ---------------------------------------------------------------------------
// Main: one block per batch row, 128 threads; thread t owns columns 4t..4t+3.
// ---------------------------------------------------------------------------
__global__ __launch_bounds__(128) void ddpm_kernel(
    const int*   __restrict__ x0,
    const int*   __restrict__ tsteps,
    const float* __restrict__ uni,
    const float* __restrict__ W,
    const float* __restrict__ bias,
    const float* __restrict__ temb)
{
    const int b   = blockIdx.x;
    const int tid = threadIdx.x;

    __shared__ float sm[DCOLS];
    __shared__ int   s_col0[FEAT];
    __shared__ int   s_w[FEAT];
    __shared__ int   s_woff[FEAT];
    __shared__ float s_lse[FEAT];
    __shared__ float s_lp0[FEAT], s_lpo[FEAT];
    __shared__ float s_q1w[FEAT], s_q1o[FEAT];
    __shared__ float s_lt[FEAT][3], s_elt[FEAT][3];   // class: 0=other,1=c0,2=w
    __shared__ float s_red[3][4];

    const int   t     = tsteps[b];
    const float lca   = g_lca[t],  l1mca  = g_l1mca[t];
    const float la    = g_la[t],   l1ma   = g_l1ma[t];
    const int   tm1   = (t > 0) ? t - 1 : 0;
    const float lca1  = g_lca[tm1], l1mca1 = g_l1mca[tm1];

    // per-feature constants + x0 columns (precise math: only 40 threads)
    if (tid < FEAT) {
        int f = tid, g = f / 5, k = f - 5 * g;
        int start = g * 62 + c_off[k];
        float lognc = c_lognc[k];
        s_col0[f] = start + x0[b * FEAT + f];
        s_lp0[f]  = lae(lca,        l1mca - lognc);   // q_prior at x0 col
        s_lpo[f]  = lae(CLOG + lca, l1mca - lognc);   // q_prior elsewhere
        s_q1w[f]  = lae(la,         l1ma - lognc);    // q_one_timestep at xt col
        s_q1o[f]  = lae(CLOG + la,  l1ma - lognc);
    }

    const int  j0  = tid * 4;
    const bool act = (j0 < DCOLS);

    // ---- hoisted segment classification for this thread's 4 columns ----
    int   fq[4];
    float lnq[4];
    if (act) {
        #pragma unroll
        for (int q = 0; q < 4; q++) {
            int j = j0 + q;
            int g = j / 62, o = j - 62 * g;
            int k = (o < 2) ? 0 : (o < 6) ? 1 : (o < 14) ? 2 : (o < 30) ? 3 : 4;
            fq[q]  = 5 * g + k;
            lnq[q] = c_lognc[k];
        }
    }
    __syncthreads();

    // -------- phase 1: z = gumbel + q_prior logits --------
    if (act) {
        float4 u4 = *reinterpret_cast<const float4*>(uni + (size_t)b * DCOLS + j0);
        const float* up = reinterpret_cast<const float*>(&u4);
        #pragma unroll
        for (int q = 0; q < 4; q++) {
            int j = j0 + q, f = fq[q];
            float gum = -__logf(-__logf(up[q] + 1e-30f) + 1e-30f);
            float lp  = (j == s_col0[f]) ? s_lp0[f] : s_lpo[f];
            sm[j] = gum + lp;
        }
    }
    __syncthreads();

    // per-segment argmax (first-max tie break, matches reference)
    if (tid < FEAT) {
        int f = tid, g = f / 5, k = f - 5 * g;
        int start = g * 62 + c_off[k], wdt = 2 << k;
        float best = -3.4e38f; int bi = start;
        for (int j = start; j < start + wdt; j++) {
            float v = sm[j];
            if (v > best) { best = v; bi = j; }
        }
        s_w[f]    = bi;
        s_woff[f] = bi * DCOLS;
    }
    __syncthreads();

    // -------- phase 2: gather-sum of 40 W rows; pred --------
    if (act) {
        float ax = 0, ay = 0, az = 0, aw = 0;
        const float* Wb = W + j0;
        #pragma unroll 8
        for (int f = 0; f < FEAT; f++) {
            float4 v = *reinterpret_cast<const float4*>(Wb + s_woff[f]);
            ax += v.x; ay += v.y; az += v.z; aw += v.w;
        }
        float4 cs = *reinterpret_cast<const float4*>(g_colsum + j0);
        float4 bb = *reinterpret_cast<const float4*>(bias + j0);
        float4 te = *reinterpret_cast<const float4*>(temb + (size_t)t * DCOLS + j0);
        sm[j0]     = CLOG * (cs.x - ax) + bb.x + te.x;
        sm[j0 + 1] = CLOG * (cs.y - ay) + bb.y + te.y;
        sm[j0 + 2] = CLOG * (cs.z - az) + bb.z + te.z;
        sm[j0 + 3] = CLOG * (cs.w - aw) + bb.w + te.w;
    }
    __syncthreads();

    // lse(pred) per segment + closed-form TRUE posterior per class
    if (tid < FEAT) {
        int f = tid, g = f / 5, k = f - 5 * g;
        int start = g * 62 + c_off[k], wdt = 2 << k;
        float m = -3.4e38f;
        for (int j = start; j < start + wdt; j++) m = fmaxf(m, sm[j]);
        float s = 0.f;
        for (int j = start; j < start + wdt; j++) s += __expf(sm[j] - m);
        s_lse[f] = m + __logf(s);

        float lognc = c_lognc[k];
        int c0 = s_col0[f], w = s_w[f];
        float ev0 = (t == 0) ? 0.f  : lae(lca1,        l1mca1 - lognc);
        float evo = (t == 0) ? CLOG : lae(CLOG + lca1, l1mca1 - lognc);
        float q1w = s_q1w[f], q1o = s_q1o[f];
        float un_oo = evo + q1o;
        float lt0, lt1, lt2;
        if (c0 == w) {
            float un_b = ev0 + q1w;
            float mm = fmaxf(un_b, un_oo);
            float ss = expf(un_b - mm) + (float)(wdt - 1) * expf(un_oo - mm);
            float lse = mm + logf(ss);
            lt1 = un_b - lse; lt2 = lt1; lt0 = un_oo - lse;
        } else {
            float un_c0 = ev0 + q1o;
            float un_w  = evo + q1w;
            float mm = fmaxf(fmaxf(un_c0, un_w), un_oo);
            float ss = expf(un_c0 - mm) + expf(un_w - mm) + (float)(wdt - 2) * expf(un_oo - mm);
            float lse = mm + logf(ss);
            lt0 = un_oo - lse; lt1 = un_c0 - lse; lt2 = un_w - lse;
        }
        s_lt[f][0] = lt0; s_lt[f][1] = lt1; s_lt[f][2] = lt2;
        s_elt[f][0] = expf(lt0); s_elt[f][1] = expf(lt1); s_elt[f][2] = expf(lt2);
    }
    __syncthreads();

    // -------- phase 3: EST posterior (dense) --------
    float un_e[4] = {0, 0, 0, 0};
    if (act) {
        #pragma unroll
        for (int q = 0; q < 4; q++) {
            int j = j0 + q, f = fq[q];
            float lh = sm[j] - s_lse[f];                         // log_x0_hat
            float q1 = (j == s_w[f]) ? s_q1w[f] : s_q1o[f];
            float ev = (t == 0) ? lh : flae(lh + lca1, l1mca1 - lnq[q]);
            un_e[q] = ev + q1;
        }
    }
    __syncthreads();          // all reads of pred done before overwrite
    if (act) {
        #pragma unroll
        for (int q = 0; q < 4; q++) sm[j0 + q] = un_e[q];
    }
    __syncthreads();
    if (tid < FEAT) {
        int f = tid, g = f / 5, k = f - 5 * g;
        int start = g * 62 + c_off[k], wdt = 2 << k;
        float m = -3.4e38f;
        for (int j = start; j < start + wdt; j++) m = fmaxf(m, sm[j]);
        float s = 0.f;
        for (int j = start; j < start + wdt; j++) s += __expf(sm[j] - m);
        s_lse[f] = m + __logf(s);
    }
    __syncthreads();

    // -------- phase 4: losses --------
    float kl = 0.f, dec = 0.f, pr = 0.f;
    if (act) {
        #pragma unroll
        for (int q = 0; q < 4; q++) {
            int j = j0 + q, f = fq[q];
            float le = un_e[q] - s_lse[f];
            bool isc0 = (j == s_col0[f]);
            int cls = isc0 ? 1 : ((j == s_w[f]) ? 2 : 0);
            kl += s_elt[f][cls] * (s_lt[f][cls] - le);
            if (isc0) dec -= le;
        }
    }
    if (tid < FEAT) {   // kl_prior closed form per feature
        int k = tid % 5;
        float lognc = c_lognc[k];
        int wdt = 2 << k;
        float lcaT = g_lca[NT - 1], l1mcaT = g_l1mca[NT - 1];
        float lq0 = lae(lcaT,        l1mcaT - lognc);
        float lqo = lae(CLOG + lcaT, l1mcaT - lognc);
        pr = expf(lq0) * (lq0 + lognc) + (float)(wdt - 1) * (expf(lqo) * (lqo + lognc));
    }

    float rk = wred(kl), rd = wred(dec), rp = wred(pr);
    int wid = tid >> 5, lane = tid & 31;
    if (lane == 0) { s_red[0][wid] = rk; s_red[1][wid] = rd; s_red[2][wid] = rp; }
    __syncthreads();
    if (tid == 0) {
        float K  = s_red[0][0] + s_red[0][1] + s_red[0][2] + s_red[0][3];
        float Dn = s_red[1][0] + s_red[1][1] + s_red[1][2] + s_red[1][3];
        float P  = s_red[2][0] + s_red[2][1] + s_red[2][2] + s_red[2][3];
        float diff = (t == 0) ? Dn : K;
        g_row_loss[b] = diff * 1000.0f + P;
    }
}

__global__ void reduce_kernel(float* __restrict__ out) {
    __shared__ double sd[32];
    int tid = threadIdx.x;
    double s = 0.0;
    for (int i = tid; i < BATCH; i += 1024) s += (double)g_row_loss[i];
    #pragma unroll
    for (int o = 16; o; o >>= 1) s += __shfl_down_sync(0xffffffffu, s, o);
    if ((tid & 31) == 0) sd[tid >> 5] = s;
    __syncthreads();
    if (tid < 32) {
        double v = sd[tid];
        #pragma unroll
        for (int o = 16; o; o >>= 1) v += __shfl_down_sync(0xffffffffu, v, o);
        if (tid == 0) out[0] = (float)(v / (double)BATCH);
    }
}

extern "C" void kernel_launch(void* const* d_in, const int* in_sizes, int n_in,
                              void* d_out, int out_size)
{
    const int*   x0 = nullptr;  const int*   ts = nullptr;
    const float* un = nullptr;  const float* W  = nullptr;
    const float* bi = nullptr;  const float* te = nullptr;
    for (int i = 0; i < n_in; i++) {
        switch (in_sizes[i]) {
            case BATCH * FEAT:   x0 = (const int*)d_in[i];   break;
            case BATCH:          ts = (const int*)d_in[i];   break;
            case BATCH * DCOLS:  un = (const float*)d_in[i]; break;
            case DCOLS * DCOLS:  W  = (const float*)d_in[i]; break;
            case DCOLS:          bi = (const float*)d_in[i]; break;
            case NT * DCOLS:     te = (const float*)d_in[i]; break;
            default: break;
        }
    }
    float* out = (float*)d_out;

    sched_kernel<<<1, 1024>>>();
    dim3 gcs(4, 8);
    cs_part_kernel<<<gcs, 128>>>(W);
    cs_comb_kernel<<<4, 128>>>();
    ddpm_kernel<<<BATCH, 128>>>(x0, ts, un, W, bi, te);
    reduce_kernel<<<1, 1024>>>(out);
}

// round 5
// speedup vs baseline: 1.2008x; 1.1148x over previous
#include <cuda_runtime.h>
#include <math.h>

#define BATCH 32768
#define FEAT  40
#define DCOLS 496
#define NT    1000

__device__ float g_la[NT], g_l1ma[NT], g_lca[NT], g_l1mca[NT];
__device__ float g_cs_part[8][DCOLS];
__device__ float g_colsum[DCOLS];
__device__ float g_row_loss[BATCH];

__constant__ float c_lognc[5] = {0.69314718055994531f, 1.38629436111989062f,
                                 2.07944154167983593f, 2.77258872223978124f,
                                 3.46573590279972655f};
__constant__ int c_off[5] = {0, 2, 6, 14, 30};

#define CLOG (-69.07755278982137f)   // log(1e-30)

// precise (only on 40 scanner/setup threads)
__device__ __forceinline__ float lae(float a, float b) {
    float mx = fmaxf(a, b);
    return mx + log1pf(expf(-fabsf(a - b)));
}
// fast logaddexp for the dense per-column path
__device__ __forceinline__ float flae(float a, float b) {
    float mx = fmaxf(a, b);
    return mx + __logf(1.0f + __expf(-fabsf(a - b)));
}

__device__ __forceinline__ float wred(float v) {
    #pragma unroll
    for (int o = 16; o; o >>= 1) v += __shfl_down_sync(0xffffffffu, v, o);
    return v;
}

// ---------------------------------------------------------------------------
// Diffusion schedule in float.
// ---------------------------------------------------------------------------
__global__ void sched_kernel() {
    __shared__ float s[1024];
    int t = threadIdx.x;
    float la = 0.0f;
    if (t < NT) {
        float beta = (t == NT - 1) ? 0.02f : (1e-4f + (float)t * ((0.02f - 1e-4f) / 999.0f));
        la = log1pf(-beta);
        g_la[t]   = la;
        g_l1ma[t] = logf(beta);
    }
    s[t] = la;
    __syncthreads();
    for (int off = 1; off < 1024; off <<= 1) {
        float v = (t >= off) ? s[t - off] : 0.0f;
        __syncthreads();
        s[t] += v;
        __syncthreads();
    }
    if (t < NT) {
        float lc = s[t];
        g_lca[t]   = lc;
        g_l1mca[t] = logf(-expm1f(lc));
    }
}

// ---------------------------------------------------------------------------
// colsum[j] = sum_d W[d][j], deterministic two-stage.
// ---------------------------------------------------------------------------
__global__ void cs_part_kernel(const float* __restrict__ W) {
    int j = blockIdx.x * 128 + threadIdx.x;
    int r0 = blockIdx.y * 62;
    if (j < DCOLS) {
        float s0 = 0.f, s1 = 0.f;
        #pragma unroll
        for (int d = 0; d < 62; d += 2) {
            s0 += W[(size_t)(r0 + d) * DCOLS + j];
            s1 += W[(size_t)(r0 + d + 1) * DCOLS + j];
        }
        g_cs_part[blockIdx.y][j] = s0 + s1;
    }
}

__global__ void cs_comb_kernel() {
    int j = blockIdx.x * 128 + threadIdx.x;
    if (j < DCOLS) {
        float s = 0.f;
        #pragma unroll
        for (int i = 0; i < 8; i++) s += g_cs_part[i][j];
        g_colsum[j] = s;
    }
}

// ---------------------------------------------------------------------------
// Main: one block per batch row, 128 threads; thread t owns columns 4t..4t+3.
// __launch_bounds__(128,16) caps registers at 32 for full occupancy.
// ---------------------------------------------------------------------------
__global__ void __launch_bounds__(128, 16) ddpm_kernel(
    const int*   __restrict__ x0,
    const int*   __restrict__ tsteps,
    const float* __restrict__ uni,
    const float* __restrict__ W,
    const float* __restrict__ bias,
    const float* __restrict__ temb)
{
    const int b   = blockIdx.x;
    const int tid = threadIdx.x;

    __shared__ float sm[DCOLS];
    __shared__ float sm2[DCOLS];
    __shared__ int   s_col0[FEAT];
    __shared__ int   s_w[FEAT];
    __shared__ int   s_woff[FEAT];
    __shared__ float s_lse[FEAT];
    __shared__ float s_lp0[FEAT], s_lpo[FEAT];
    __shared__ float s_q1w[FEAT], s_q1o[FEAT];
    __shared__ float s_evc[FEAT];                     // l1mca1 - lognc (per feature)
    __shared__ float s_lt[FEAT][3], s_elt[FEAT][3];   // class: 0=other,1=c0,2=w
    __shared__ float s_red[3][4];

    const int t = tsteps[b];

    // per-feature constants + x0 columns (precise math: only 40 threads)
    if (tid < FEAT) {
        const float lca   = g_lca[t],  l1mca = g_l1mca[t];
        const float la    = g_la[t],   l1ma  = g_l1ma[t];
        const int   tm1   = (t > 0) ? t - 1 : 0;
        const float l1mca1 = g_l1mca[tm1];
        int f = tid, g = f / 5, k = f - 5 * g;
        int start = g * 62 + c_off[k];
        float lognc = c_lognc[k];
        s_col0[f] = start + x0[b * FEAT + f];
        s_lp0[f]  = lae(lca,        l1mca - lognc);   // q_prior at x0 col
        s_lpo[f]  = lae(CLOG + lca, l1mca - lognc);   // q_prior elsewhere
        s_q1w[f]  = lae(la,         l1ma - lognc);    // q_one_timestep at xt col
        s_q1o[f]  = lae(CLOG + la,  l1ma - lognc);
        s_evc[f]  = l1mca1 - lognc;
    }

    const int  j0  = tid * 4;
    const bool act = (j0 < DCOLS);

    // ---- packed segment classification for this thread's 4 columns ----
    unsigned int fpack = 0;
    if (act) {
        #pragma unroll
        for (int q = 0; q < 4; q++) {
            int j = j0 + q;
            int g = j / 62, o = j - 62 * g;
            int k = (o < 2) ? 0 : (o < 6) ? 1 : (o < 14) ? 2 : (o < 30) ? 3 : 4;
            fpack |= (unsigned int)(5 * g + k) << (8 * q);
        }
    }
    __syncthreads();

    // -------- phase 1: z = gumbel + q_prior logits --------
    if (act) {
        float4 u4 = *reinterpret_cast<const float4*>(uni + (size_t)b * DCOLS + j0);
        const float* up = reinterpret_cast<const float*>(&u4);
        #pragma unroll
        for (int q = 0; q < 4; q++) {
            int j = j0 + q;
            int f = (fpack >> (8 * q)) & 0xff;
            float gum = -__logf(-__logf(up[q] + 1e-30f) + 1e-30f);
            float lp  = (j == s_col0[f]) ? s_lp0[f] : s_lpo[f];
            sm[j] = gum + lp;
        }
    }
    __syncthreads();

    // per-segment argmax (first-max tie break, matches reference)
    if (tid < FEAT) {
        int f = tid, g = f / 5, k = f - 5 * g;
        int start = g * 62 + c_off[k], wdt = 2 << k;
        float best = -3.4e38f; int bi = start;
        for (int j = start; j < start + wdt; j++) {
            float v = sm[j];
            if (v > best) { best = v; bi = j; }
        }
        s_w[f]    = bi;
        s_woff[f] = bi * DCOLS;
    }
    __syncthreads();

    // -------- phase 2: gather-sum of 40 W rows; pred --------
    if (act) {
        float ax = 0, ay = 0, az = 0, aw = 0;
        const float* Wb = W + j0;
        #pragma unroll 8
        for (int f = 0; f < FEAT; f++) {
            float4 v = *reinterpret_cast<const float4*>(Wb + s_woff[f]);
            ax += v.x; ay += v.y; az += v.z; aw += v.w;
        }
        float4 cs = *reinterpret_cast<const float4*>(g_colsum + j0);
        float4 bb = *reinterpret_cast<const float4*>(bias + j0);
        float4 te = *reinterpret_cast<const float4*>(temb + (size_t)t * DCOLS + j0);
        sm[j0]     = CLOG * (cs.x - ax) + bb.x + te.x;
        sm[j0 + 1] = CLOG * (cs.y - ay) + bb.y + te.y;
        sm[j0 + 2] = CLOG * (cs.z - az) + bb.z + te.z;
        sm[j0 + 3] = CLOG * (cs.w - aw) + bb.w + te.w;
    }
    __syncthreads();

    // lse(pred) per segment + closed-form TRUE posterior per class
    if (tid < FEAT) {
        const int   tm1    = (t > 0) ? t - 1 : 0;
        const float lca1   = g_lca[tm1], l1mca1 = g_l1mca[tm1];
        int f = tid, g = f / 5, k = f - 5 * g;
        int start = g * 62 + c_off[k], wdt = 2 << k;
        float m = -3.4e38f;
        for (int j = start; j < start + wdt; j++) m = fmaxf(m, sm[j]);
        float s = 0.f;
        for (int j = start; j < start + wdt; j++) s += __expf(sm[j] - m);
        s_lse[f] = m + __logf(s);

        float lognc = c_lognc[k];
        int c0 = s_col0[f], w = s_w[f];
        float ev0 = (t == 0) ? 0.f  : lae(lca1,        l1mca1 - lognc);
        float evo = (t == 0) ? CLOG : lae(CLOG + lca1, l1mca1 - lognc);
        float q1w = s_q1w[f], q1o = s_q1o[f];
        float un_oo = evo + q1o;
        float lt0, lt1, lt2;
        if (c0 == w) {
            float un_b = ev0 + q1w;
            float mm = fmaxf(un_b, un_oo);
            float ss = expf(un_b - mm) + (float)(wdt - 1) * expf(un_oo - mm);
            float lse = mm + logf(ss);
            lt1 = un_b - lse; lt2 = lt1; lt0 = un_oo - lse;
        } else {
            float un_c0 = ev0 + q1o;
            float un_w  = evo + q1w;
            float mm = fmaxf(fmaxf(un_c0, un_w), un_oo);
            float ss = expf(un_c0 - mm) + expf(un_w - mm) + (float)(wdt - 2) * expf(un_oo - mm);
            float lse = mm + logf(ss);
            lt0 = un_oo - lse; lt1 = un_c0 - lse; lt2 = un_w - lse;
        }
        s_lt[f][0] = lt0; s_lt[f][1] = lt1; s_lt[f][2] = lt2;
        s_elt[f][0] = expf(lt0); s_elt[f][1] = expf(lt1); s_elt[f][2] = expf(lt2);
    }
    __syncthreads();

    // -------- phase 3: EST posterior (dense) --------
    if (act) {
        const int   tm1  = (t > 0) ? t - 1 : 0;
        const float lca1 = g_lca[tm1];
        #pragma unroll
        for (int q = 0; q < 4; q++) {
            int j = j0 + q;
            int f = (fpack >> (8 * q)) & 0xff;
            float lh = sm[j] - s_lse[f];                         // log_x0_hat
            float q1 = (j == s_w[f]) ? s_q1w[f] : s_q1o[f];
            float ev = (t == 0) ? lh : flae(lh + lca1, s_evc[f]);
            sm2[j] = ev + q1;
        }
    }
    __syncthreads();
    if (tid < FEAT) {
        int f = tid, g = f / 5, k = f - 5 * g;
        int start = g * 62 + c_off[k], wdt = 2 << k;
        float m = -3.4e38f;
        for (int j = start; j < start + wdt; j++) m = fmaxf(m, sm2[j]);
        float s = 0.f;
        for (int j = start; j < start + wdt; j++) s += __expf(sm2[j] - m);
        s_lse[f] = m + __logf(s);
    }
    __syncthreads();

    // -------- phase 4: losses --------
    float kl = 0.f, dec = 0.f, pr = 0.f;
    if (act) {
        #pragma unroll
        for (int q = 0; q < 4; q++) {
            int j = j0 + q;
            int f = (fpack >> (8 * q)) & 0xff;
            float le = sm2[j] - s_lse[f];
            bool isc0 = (j == s_col0[f]);
            int cls = isc0 ? 1 : ((j == s_w[f]) ? 2 : 0);
            kl += s_elt[f][cls] * (s_lt[f][cls] - le);
            if (isc0) dec -= le;
        }
    }
    if (tid < FEAT) {   // kl_prior closed form per feature
        int k = tid % 5;
        float lognc = c_lognc[k];
        int wdt = 2 << k;
        float lcaT = g_lca[NT - 1], l1mcaT = g_l1mca[NT - 1];
        float lq0 = lae(lcaT,        l1mcaT - lognc);
        float lqo = lae(CLOG + lcaT, l1mcaT - lognc);
        pr = expf(lq0) * (lq0 + lognc) + (float)(wdt - 1) * (expf(lqo) * (lqo + lognc));
    }

    float rk = wred(kl), rd = wred(dec), rp = wred(pr);
    int wid = tid >> 5, lane = tid & 31;
    if (lane == 0) { s_red[0][wid] = rk; s_red[1][wid] = rd; s_red[2][wid] = rp; }
    __syncthreads();
    if (tid == 0) {
        float K  = s_red[0][0] + s_red[0][1] + s_red[0][2] + s_red[0][3];
        float Dn = s_red[1][0] + s_red[1][1] + s_red[1][2] + s_red[1][3];
        float P  = s_red[2][0] + s_red[2][1] + s_red[2][2] + s_red[2][3];
        float diff = (t == 0) ? Dn : K;
        g_row_loss[b] = diff * 1000.0f + P;
    }
}

__global__ void reduce_kernel(float* __restrict__ out) {
    __shared__ double sd[32];
    int tid = threadIdx.x;
    double s = 0.0;
    for (int i = tid; i < BATCH; i += 1024) s += (double)g_row_loss[i];
    #pragma unroll
    for (int o = 16; o; o >>= 1) s += __shfl_down_sync(0xffffffffu, s, o);
    if ((tid & 31) == 0) sd[tid >> 5] = s;
    __syncthreads();
    if (tid < 32) {
        double v = sd[tid];
        #pragma unroll
        for (int o = 16; o; o >>= 1) v += __shfl_down_sync(0xffffffffu, v, o);
        if (tid == 0) out[0] = (float)(v / (double)BATCH);
    }
}

extern "C" void kernel_launch(void* const* d_in, const int* in_sizes, int n_in,
                              void* d_out, int out_size)
{
    const int*   x0 = nullptr;  const int*   ts = nullptr;
    const float* un = nullptr;  const float* W  = nullptr;
    const float* bi = nullptr;  const float* te = nullptr;
    for (int i = 0; i < n_in; i++) {
        switch (in_sizes[i]) {
            case BATCH * FEAT:   x0 = (const int*)d_in[i];   break;
            case BATCH:          ts = (const int*)d_in[i];   break;
            case BATCH * DCOLS:  un = (const float*)d_in[i]; break;
            case DCOLS * DCOLS:  W  = (const float*)d_in[i]; break;
            case DCOLS:          bi = (const float*)d_in[i]; break;
            case NT * DCOLS:     te = (const float*)d_in[i]; break;
            default: break;
        }
    }
    float* out = (float*)d_out;

    sched_kernel<<<1, 1024>>>();
    dim3 gcs(4, 8);
    cs_part_kernel<<<gcs, 128>>>(W);
    cs_comb_kernel<<<4, 128>>>();
    ddpm_kernel<<<BATCH, 128>>>(x0, ts, un, W, bi, te);
    reduce_kernel<<<1, 1024>>>(out);
}

// round 7
// speedup vs baseline: 1.3180x; 1.0976x over previous
#include <cuda_runtime.h>
#include <math.h>

#define BATCH 32768
#define FEAT  40
#define DCOLS 496
#define NT    1000

__device__ float g_la[NT], g_l1ma[NT], g_lca[NT], g_l1mca[NT];
__device__ float g_cs_part[8][DCOLS];
__device__ float g_colsum[DCOLS];
__device__ float g_row_loss[BATCH];

__constant__ float c_lognc[5] = {0.69314718055994531f, 1.38629436111989062f,
                                 2.07944154167983593f, 2.77258872223978124f,
                                 3.46573590279972655f};
__constant__ int c_off[5] = {0, 2, 6, 14, 30};

#define CLOG (-69.07755278982137f)   // log(1e-30)

// fast logaddexp (rel err ~1e-7, budget is 1e-3)
__device__ __forceinline__ float flae(float a, float b) {
    float mx = fmaxf(a, b);
    return mx + __logf(1.0f + __expf(-fabsf(a - b)));
}

#define ADD_F32X2(out, a, b) \
    asm("add.rn.f32x2 %0, %1, %2;" : "=l"(out) : "l"(a), "l"(b))
#define UNPACK_F32X2(lo, hi, in) \
    asm("mov.b64 {%0, %1}, %2;" : "=r"(lo), "=r"(hi) : "l"(in))

__device__ __forceinline__ float wred(float v) {
    #pragma unroll
    for (int o = 16; o; o >>= 1) v += __shfl_down_sync(0xffffffffu, v, o);
    return v;
}

// ---------------------------------------------------------------------------
// Diffusion schedule (float precision is ample at 1e-3 tolerance).
// ---------------------------------------------------------------------------
__global__ void sched_kernel() {
    __shared__ float s[1024];
    int t = threadIdx.x;
    float la = 0.0f;
    if (t < NT) {
        float beta = (t == NT - 1) ? 0.02f : (1e-4f + (float)t * ((0.02f - 1e-4f) / 999.0f));
        la = log1pf(-beta);
        g_la[t]   = la;
        g_l1ma[t] = logf(beta);
    }
    s[t] = la;
    __syncthreads();
    for (int off = 1; off < 1024; off <<= 1) {
        float v = (t >= off) ? s[t - off] : 0.0f;
        __syncthreads();
        s[t] += v;
        __syncthreads();
    }
    if (t < NT) {
        float lc = s[t];
        g_lca[t]   = lc;
        g_l1mca[t] = logf(-expm1f(lc));
    }
}

// ---------------------------------------------------------------------------
// colsum[j] = sum_d W[d][j], deterministic two-stage.
// ---------------------------------------------------------------------------
__global__ void cs_part_kernel(const float* __restrict__ W) {
    int j = blockIdx.x * 128 + threadIdx.x;
    int r0 = blockIdx.y * 62;
    if (j < DCOLS) {
        float s0 = 0.f, s1 = 0.f;
        #pragma unroll
        for (int d = 0; d < 62; d += 2) {
            s0 += W[(size_t)(r0 + d) * DCOLS + j];
            s1 += W[(size_t)(r0 + d + 1) * DCOLS + j];
        }
        g_cs_part[blockIdx.y][j] = s0 + s1;
    }
}

__global__ void cs_comb_kernel() {
    int j = blockIdx.x * 128 + threadIdx.x;
    if (j < DCOLS) {
        float s = 0.f;
        #pragma unroll
        for (int i = 0; i < 8; i++) s += g_cs_part[i][j];
        g_colsum[j] = s;
    }
}

// ---------------------------------------------------------------------------
// Main: one block per batch row, 128 threads; thread t owns columns 4t..4t+3.
// ---------------------------------------------------------------------------
__global__ void __launch_bounds__(128, 16) ddpm_kernel(
    const int*   __restrict__ x0,
    const int*   __restrict__ tsteps,
    const float* __restrict__ uni,
    const float* __restrict__ W,
    const float* __restrict__ bias,
    const float* __restrict__ temb)
{
    const int b   = blockIdx.x;
    const int tid = threadIdx.x;

    __shared__ __align__(16) float sm[DCOLS];
    __shared__ __align__(16) float sm2[DCOLS];
    __shared__ int   s_col0[FEAT];
    __shared__ int   s_w[FEAT];
    __shared__ int   s_wbyte[FEAT];
    __shared__ float s_lse[FEAT];
    __shared__ float s_lp0[FEAT], s_lpo[FEAT];
    __shared__ float s_q1w[FEAT], s_q1o[FEAT];
    __shared__ float s_evc[FEAT];              // l1mca1 - lognc
    __shared__ float s_elt[FEAT][3];           // exp(log_true) per class 0=other,1=c0,2=w
    __shared__ float s_klc[FEAT];              // sum_j p*lt  (constant KL part)
    __shared__ float s_red[3][4];

    const int t = tsteps[b];

    // per-feature constants + x0 columns
    if (tid < FEAT) {
        const float lca   = g_lca[t],  l1mca = g_l1mca[t];
        const float la    = g_la[t],   l1ma  = g_l1ma[t];
        const int   tm1   = (t > 0) ? t - 1 : 0;
        const float l1mca1 = g_l1mca[tm1];
        int f = tid, g = f / 5, k = f - 5 * g;
        int start = g * 62 + c_off[k];
        float lognc = c_lognc[k];
        s_col0[f] = start + x0[b * FEAT + f];
        s_lp0[f]  = flae(lca,        l1mca - lognc);
        s_lpo[f]  = flae(CLOG + lca, l1mca - lognc);
        s_q1w[f]  = flae(la,         l1ma - lognc);
        s_q1o[f]  = flae(CLOG + la,  l1ma - lognc);
        s_evc[f]  = l1mca1 - lognc;
    }

    const int  j0  = tid * 4;
    const bool act = (j0 < DCOLS);

    // packed feature ids for this thread's 4 columns
    unsigned int fpack = 0;
    if (act) {
        #pragma unroll
        for (int q = 0; q < 4; q++) {
            int j = j0 + q;
            int g = j / 62, o = j - 62 * g;
            int k = (o < 2) ? 0 : (o < 6) ? 1 : (o < 14) ? 2 : (o < 30) ? 3 : 4;
            fpack |= (unsigned int)(5 * g + k) << (8 * q);
        }
    }
    __syncthreads();

    // -------- phase 1: z = gumbel + q_prior logits --------
    if (act) {
        float4 u4 = *reinterpret_cast<const float4*>(uni + (size_t)b * DCOLS + j0);
        const float* up = reinterpret_cast<const float*>(&u4);
        float4 z; float* zp = reinterpret_cast<float*>(&z);
        #pragma unroll
        for (int q = 0; q < 4; q++) {
            int j = j0 + q;
            int f = (fpack >> (8 * q)) & 0xff;
            float gum = -__logf(-__logf(up[q] + 1e-30f) + 1e-30f);
            float lp  = (j == s_col0[f]) ? s_lp0[f] : s_lpo[f];
            zp[q] = gum + lp;
        }
        *reinterpret_cast<float4*>(sm + j0) = z;
    }
    __syncthreads();

    // per-segment argmax (first-max tie break; segment starts are even -> float2)
    if (tid < FEAT) {
        int f = tid, g = f / 5, k = f - 5 * g;
        int start = g * 62 + c_off[k], n2 = (2 << k) >> 1;
        const float2* p2 = reinterpret_cast<const float2*>(sm + start);
        float best = -3.4e38f; int bi = 0;
        for (int i = 0; i < n2; i++) {
            float2 v = p2[i];
            if (v.x > best) { best = v.x; bi = 2 * i; }
            if (v.y > best) { best = v.y; bi = 2 * i + 1; }
        }
        int w = start + bi;
        s_w[f]     = w;
        s_wbyte[f] = w * (DCOLS * 4);
    }
    __syncthreads();

    // -------- phase 2: gather-sum of 40 W rows (packed f32x2 adds) --------
    if (act) {
        unsigned long long a01 = 0ull, a23 = 0ull;
        const char* Wb = (const char*)W + (size_t)j0 * 4;
        #pragma unroll 8
        for (int f = 0; f < FEAT; f++) {
            ulonglong2 v = *reinterpret_cast<const ulonglong2*>(Wb + s_wbyte[f]);
            ADD_F32X2(a01, a01, v.x);
            ADD_F32X2(a23, a23, v.y);
        }
        unsigned int ux, uy, uz, uw;
        UNPACK_F32X2(ux, uy, a01);
        UNPACK_F32X2(uz, uw, a23);
        float ax = __uint_as_float(ux), ay = __uint_as_float(uy);
        float az = __uint_as_float(uz), aw = __uint_as_float(uw);
        float4 cs = *reinterpret_cast<const float4*>(g_colsum + j0);
        float4 bb = *reinterpret_cast<const float4*>(bias + j0);
        float4 te = *reinterpret_cast<const float4*>(temb + (size_t)t * DCOLS + j0);
        float4 pr4;
        pr4.x = CLOG * (cs.x - ax) + bb.x + te.x;
        pr4.y = CLOG * (cs.y - ay) + bb.y + te.y;
        pr4.z = CLOG * (cs.z - az) + bb.z + te.z;
        pr4.w = CLOG * (cs.w - aw) + bb.w + te.w;
        *reinterpret_cast<float4*>(sm + j0) = pr4;
    }
    __syncthreads();

    // lse(pred) per segment + closed-form TRUE posterior + constant KL part
    if (tid < FEAT) {
        const int   tm1    = (t > 0) ? t - 1 : 0;
        const float lca1   = g_lca[tm1], l1mca1 = g_l1mca[tm1];
        int f = tid, g = f / 5, k = f - 5 * g;
        int start = g * 62 + c_off[k], wdt = 2 << k, n2 = wdt >> 1;
        const float2* p2 = reinterpret_cast<const float2*>(sm + start);
        float m = -3.4e38f;
        for (int i = 0; i < n2; i++) {
            float2 v = p2[i];
            m = fmaxf(m, fmaxf(v.x, v.y));
        }
        float s = 0.f;
        for (int i = 0; i < n2; i++) {
            float2 v = p2[i];
            s += __expf(v.x - m) + __expf(v.y - m);
        }
        s_lse[f] = m + __logf(s);

        float lognc = c_lognc[k];
        int c0 = s_col0[f], w = s_w[f];
        float ev0 = (t == 0) ? 0.f  : flae(lca1,        l1mca1 - lognc);
        float evo = (t == 0) ? CLOG : flae(CLOG + lca1, l1mca1 - lognc);
        float q1w = s_q1w[f], q1o = s_q1o[f];
        float un_oo = evo + q1o;
        float lt0, lt1, lt2, klc;
        if (c0 == w) {
            float un_b = ev0 + q1w;
            float mm = fmaxf(un_b, un_oo);
            float ss = __expf(un_b - mm) + (float)(wdt - 1) * __expf(un_oo - mm);
            float lse = mm + __logf(ss);
            lt1 = un_b - lse; lt2 = lt1; lt0 = un_oo - lse;
            float e0 = __expf(lt0), e1 = __expf(lt1);
            s_elt[f][0] = e0; s_elt[f][1] = e1; s_elt[f][2] = e1;
            klc = e1 * lt1 + (float)(wdt - 1) * e0 * lt0;
        } else {
            float un_c0 = ev0 + q1o;
            float un_w  = evo + q1w;
            float mm = fmaxf(fmaxf(un_c0, un_w), un_oo);
            float ss = __expf(un_c0 - mm) + __expf(un_w - mm) + (float)(wdt - 2) * __expf(un_oo - mm);
            float lse = mm + __logf(ss);
            lt0 = un_oo - lse; lt1 = un_c0 - lse; lt2 = un_w - lse;
            float e0 = __expf(lt0), e1 = __expf(lt1), e2 = __expf(lt2);
            s_elt[f][0] = e0; s_elt[f][1] = e1; s_elt[f][2] = e2;
            klc = e1 * lt1 + e2 * lt2 + (float)(wdt - 2) * e0 * lt0;
        }
        s_klc[f] = klc;
    }
    __syncthreads();

    // -------- phase 3: EST posterior (dense) --------
    if (act) {
        const int   tm1  = (t > 0) ? t - 1 : 0;
        const float lca1 = g_lca[tm1];
        float4 pv = *reinterpret_cast<const float4*>(sm + j0);
        const float* pp = reinterpret_cast<const float*>(&pv);
        float4 ue; float* up = reinterpret_cast<float*>(&ue);
        #pragma unroll
        for (int q = 0; q < 4; q++) {
            int j = j0 + q;
            int f = (fpack >> (8 * q)) & 0xff;
            float lh = pp[q] - s_lse[f];
            float q1 = (j == s_w[f]) ? s_q1w[f] : s_q1o[f];
            float ev = (t == 0) ? lh : flae(lh + lca1, s_evc[f]);
            up[q] = ev + q1;
        }
        *reinterpret_cast<float4*>(sm2 + j0) = ue;
    }
    __syncthreads();
    if (tid < FEAT) {
        int f = tid, g = f / 5, k = f - 5 * g;
        int start = g * 62 + c_off[k], n2 = (2 << k) >> 1;
        const float2* p2 = reinterpret_cast<const float2*>(sm2 + start);
        float m = -3.4e38f;
        for (int i = 0; i < n2; i++) {
            float2 v = p2[i];
            m = fmaxf(m, fmaxf(v.x, v.y));
        }
        float s = 0.f;
        for (int i = 0; i < n2; i++) {
            float2 v = p2[i];
            s += __expf(v.x - m) + __expf(v.y - m);
        }
        s_lse[f] = m + __logf(s);
    }
    __syncthreads();

    // -------- phase 4: losses --------
    float kl = 0.f, dec = 0.f, pr = 0.f;
    if (act) {
        float4 uv = *reinterpret_cast<const float4*>(sm2 + j0);
        const float* up = reinterpret_cast<const float*>(&uv);
        #pragma unroll
        for (int q = 0; q < 4; q++) {
            int j = j0 + q;
            int f = (fpack >> (8 * q)) & 0xff;
            float le = up[q] - s_lse[f];
            bool isc0 = (j == s_col0[f]);
            int cls = isc0 ? 1 : ((j == s_w[f]) ? 2 : 0);
            kl -= s_elt[f][cls] * le;          // -sum p*le  (per-column part)
            if (isc0) dec -= le;
        }
    }
    if (tid < FEAT) kl += s_klc[tid];          // +sum p*lt  (constant part)
    if (tid < 5) {                              // kl_prior: 5 distinct values x 8 groups
        float lognc = c_lognc[tid];
        float wdt = (float)(2 << tid);
        float lcaT = g_lca[NT - 1], l1mcaT = g_l1mca[NT - 1];
        float lq0 = flae(lcaT,        l1mcaT - lognc);
        float lqo = flae(CLOG + lcaT, l1mcaT - lognc);
        pr = 8.0f * (__expf(lq0) * (lq0 + lognc) + (wdt - 1.0f) * __expf(lqo) * (lqo + lognc));
    }

    float rk = wred(kl), rd = wred(dec), rp = wred(pr);
    int wid = tid >> 5, lane = tid & 31;
    if (lane == 0) { s_red[0][wid] = rk; s_red[1][wid] = rd; s_red[2][wid] = rp; }
    __syncthreads();
    if (tid == 0) {
        float K  = s_red[0][0] + s_red[0][1] + s_red[0][2] + s_red[0][3];
        float Dn = s_red[1][0] + s_red[1][1] + s_red[1][2] + s_red[1][3];
        float P  = s_red[2][0] + s_red[2][1] + s_red[2][2] + s_red[2][3];
        float diff = (t == 0) ? Dn : K;
        g_row_loss[b] = diff * 1000.0f + P;
    }
}

__global__ void reduce_kernel(float* __restrict__ out) {
    __shared__ double sd[32];
    int tid = threadIdx.x;
    double s = 0.0;
    const float4* rl = reinterpret_cast<const float4*>(g_row_loss);
    for (int i = tid; i < BATCH / 4; i += 1024) {
        float4 v = rl[i];
        s += (double)v.x + (double)v.y + (double)v.z + (double)v.w;
    }
    #pragma unroll
    for (int o = 16; o; o >>= 1) s += __shfl_down_sync(0xffffffffu, s, o);
    if ((tid & 31) == 0) sd[tid >> 5] = s;
    __syncthreads();
    if (tid < 32) {
        double v = sd[tid];
        #pragma unroll
        for (int o = 16; o; o >>= 1) v += __shfl_down_sync(0xffffffffu, v, o);
        if (tid == 0) out[0] = (float)(v / (double)BATCH);
    }
}

extern "C" void kernel_launch(void* const* d_in, const int* in_sizes, int n_in,
                              void* d_out, int out_size)
{
    const int*   x0 = nullptr;  const int*   ts = nullptr;
    const float* un = nullptr;  const float* W  = nullptr;
    const float* bi = nullptr;  const float* te = nullptr;
    for (int i = 0; i < n_in; i++) {
        switch (in_sizes[i]) {
            case BATCH * FEAT:   x0 = (const int*)d_in[i];   break;
            case BATCH:          ts = (const int*)d_in[i];   break;
            case BATCH * DCOLS:  un = (const float*)d_in[i]; break;
            case DCOLS * DCOLS:  W  = (const float*)d_in[i]; break;
            case DCOLS:          bi = (const float*)d_in[i]; break;
            case NT * DCOLS:     te = (const float*)d_in[i]; break;
            default: break;
        }
    }
    float* out = (float*)d_out;

    sched_kernel<<<1, 1024>>>();
    dim3 gcs(4, 8);
    cs_part_kernel<<<gcs, 128>>>(W);
    cs_comb_kernel<<<4, 128>>>();
    ddpm_kernel<<<BATCH, 128>>>(x0, ts, un, W, bi, te);
    reduce_kernel<<<1, 1024>>>(out);
}

// round 8
// speedup vs baseline: 1.4071x; 1.0676x over previous
#include <cuda_runtime.h>
#include <math.h>

#define BATCH 32768
#define FEAT  40
#define DCOLS 496
#define NT    1000

__device__ float g_la[NT], g_l1ma[NT], g_lca[NT], g_l1mca[NT];
__device__ float g_cs_part[8][DCOLS];
__device__ float g_colsum[DCOLS];
__device__ float g_row_loss[BATCH];

__constant__ float c_lognc[5] = {0.69314718055994531f, 1.38629436111989062f,
                                 2.07944154167983593f, 2.77258872223978124f,
                                 3.46573590279972655f};
__constant__ int c_off[5] = {0, 2, 6, 14, 30};

#define CLOG (-69.07755278982137f)   // log(1e-30)

// fast logaddexp (rel err ~1e-7, budget is 1e-3)
__device__ __forceinline__ float flae(float a, float b) {
    float mx = fmaxf(a, b);
    return mx + __logf(1.0f + __expf(-fabsf(a - b)));
}

#define ADD_F32X2(out, a, b) \
    asm("add.rn.f32x2 %0, %1, %2;" : "=l"(out) : "l"(a), "l"(b))
#define UNPACK_F32X2(lo, hi, in) \
    asm("mov.b64 {%0, %1}, %2;" : "=r"(lo), "=r"(hi) : "l"(in))

__device__ __forceinline__ float wred(float v) {
    #pragma unroll
    for (int o = 16; o; o >>= 1) v += __shfl_down_sync(0xffffffffu, v, o);
    return v;
}

// ---------------------------------------------------------------------------
// Diffusion schedule (float precision is ample at 1e-3 tolerance).
// ---------------------------------------------------------------------------
__global__ void sched_kernel() {
    __shared__ float s[1024];
    int t = threadIdx.x;
    float la = 0.0f;
    if (t < NT) {
        float beta = (t == NT - 1) ? 0.02f : (1e-4f + (float)t * ((0.02f - 1e-4f) / 999.0f));
        la = log1pf(-beta);
        g_la[t]   = la;
        g_l1ma[t] = logf(beta);
    }
    s[t] = la;
    __syncthreads();
    for (int off = 1; off < 1024; off <<= 1) {
        float v = (t >= off) ? s[t - off] : 0.0f;
        __syncthreads();
        s[t] += v;
        __syncthreads();
    }
    if (t < NT) {
        float lc = s[t];
        g_lca[t]   = lc;
        g_l1mca[t] = logf(-expm1f(lc));
    }
}

// ---------------------------------------------------------------------------
// colsum[j] = sum_d W[d][j], deterministic two-stage.
// ---------------------------------------------------------------------------
__global__ void cs_part_kernel(const float* __restrict__ W) {
    int j = blockIdx.x * 128 + threadIdx.x;
    int r0 = blockIdx.y * 62;
    if (j < DCOLS) {
        float s0 = 0.f, s1 = 0.f;
        #pragma unroll
        for (int d = 0; d < 62; d += 2) {
            s0 += W[(size_t)(r0 + d) * DCOLS + j];
            s1 += W[(size_t)(r0 + d + 1) * DCOLS + j];
        }
        g_cs_part[blockIdx.y][j] = s0 + s1;
    }
}

__global__ void cs_comb_kernel() {
    int j = blockIdx.x * 128 + threadIdx.x;
    if (j < DCOLS) {
        float s = 0.f;
        #pragma unroll
        for (int i = 0; i < 8; i++) s += g_cs_part[i][j];
        g_colsum[j] = s;
    }
}

// ---------------------------------------------------------------------------
// Main: one block per batch row, 128 threads; thread t owns columns 4t..4t+3.
// ---------------------------------------------------------------------------
__global__ void __launch_bounds__(128, 16) ddpm_kernel(
    const int*   __restrict__ x0,
    const int*   __restrict__ tsteps,
    const float* __restrict__ uni,
    const float* __restrict__ W,
    const float* __restrict__ bias,
    const float* __restrict__ temb)
{
    const int b   = blockIdx.x;
    const int tid = threadIdx.x;

    __shared__ __align__(16) float sm[DCOLS];
    __shared__ int    s_col0[FEAT];
    __shared__ int    s_wbyte[FEAT];
    __shared__ float2 s_lp[FEAT];      // {lpo, lp0} q_prior logits
    __shared__ float4 s_fc[FEAT];      // {lse_pred, e0, B, unused} for dense accum
    __shared__ float  s_red[3][4];

    const int   t    = tsteps[b];
    const int   tm1  = (t > 0) ? t - 1 : 0;
    const float lca1 = g_lca[tm1], l1mca1 = g_l1mca[tm1];
    const float Aev  = (t == 0) ? 1.0f : __expf(lca1);     // uniform per block

    // scanner-thread persistent state
    int c0 = 0, w = 0;

    // -------- setup: per-feature q_prior logits + x0 column --------
    if (tid < FEAT) {
        const float lca = g_lca[t], l1mca = g_l1mca[t];
        int f = tid, g = f / 5, k = f - 5 * g;
        int start = g * 62 + c_off[k];
        float lognc = c_lognc[k];
        c0 = start + x0[b * FEAT + f];
        s_col0[f] = c0;
        s_lp[f] = make_float2(flae(CLOG + lca, l1mca - lognc),   // elsewhere
                              flae(lca,        l1mca - lognc));  // at x0 col
    }

    const int  j0  = tid * 4;
    const bool act = (j0 < DCOLS);

    // packed feature ids for this thread's 4 columns
    unsigned int fpack = 0;
    if (act) {
        #pragma unroll
        for (int q = 0; q < 4; q++) {
            int j = j0 + q;
            int g = j / 62, o = j - 62 * g;
            int k = (o < 2) ? 0 : (o < 6) ? 1 : (o < 14) ? 2 : (o < 30) ? 3 : 4;
            fpack |= (unsigned int)(5 * g + k) << (8 * q);
        }
    }
    __syncthreads();

    // -------- phase 1: z = gumbel + q_prior logits --------
    if (act) {
        float4 u4 = *reinterpret_cast<const float4*>(uni + (size_t)b * DCOLS + j0);
        const float* up = reinterpret_cast<const float*>(&u4);
        float4 z; float* zp = reinterpret_cast<float*>(&z);
        #pragma unroll
        for (int q = 0; q < 4; q++) {
            int j = j0 + q;
            int f = (fpack >> (8 * q)) & 0xff;
            float gum = -__logf(-__logf(up[q] + 1e-30f) + 1e-30f);
            float2 lp = s_lp[f];
            zp[q] = gum + ((j == s_col0[f]) ? lp.y : lp.x);
        }
        *reinterpret_cast<float4*>(sm + j0) = z;
    }
    __syncthreads();

    // per-segment argmax (first-max tie break; segment starts even -> float2)
    if (tid < FEAT) {
        int f = tid, g = f / 5, k = f - 5 * g;
        int start = g * 62 + c_off[k], n2 = (2 << k) >> 1;
        const float2* p2 = reinterpret_cast<const float2*>(sm + start);
        float best = -3.4e38f; int bi = 0;
        for (int i = 0; i < n2; i++) {
            float2 v = p2[i];
            if (v.x > best) { best = v.x; bi = 2 * i; }
            if (v.y > best) { best = v.y; bi = 2 * i + 1; }
        }
        w = start + bi;
        s_wbyte[f] = w * (DCOLS * 4);
    }
    __syncthreads();

    // -------- phase 2: gather-sum of 40 W rows (packed f32x2 adds) --------
    if (act) {
        unsigned long long a01 = 0ull, a23 = 0ull;
        const char* Wb = (const char*)W + (size_t)j0 * 4;
        #pragma unroll 8
        for (int f = 0; f < FEAT; f++) {
            ulonglong2 v = *reinterpret_cast<const ulonglong2*>(Wb + s_wbyte[f]);
            ADD_F32X2(a01, a01, v.x);
            ADD_F32X2(a23, a23, v.y);
        }
        unsigned int ux, uy, uz, uw;
        UNPACK_F32X2(ux, uy, a01);
        UNPACK_F32X2(uz, uw, a23);
        float ax = __uint_as_float(ux), ay = __uint_as_float(uy);
        float az = __uint_as_float(uz), aw = __uint_as_float(uw);
        float4 cs = *reinterpret_cast<const float4*>(g_colsum + j0);
        float4 bb = *reinterpret_cast<const float4*>(bias + j0);
        float4 te = *reinterpret_cast<const float4*>(temb + (size_t)t * DCOLS + j0);
        float4 pr4;
        pr4.x = CLOG * (cs.x - ax) + bb.x + te.x;
        pr4.y = CLOG * (cs.y - ay) + bb.y + te.y;
        pr4.z = CLOG * (cs.z - az) + bb.z + te.z;
        pr4.w = CLOG * (cs.w - aw) + bb.w + te.w;
        *reinterpret_cast<float4*>(sm + j0) = pr4;
    }
    __syncthreads();

    // -------- scanner: lse(pred), true posterior, closed-form lse2, corrections --
    float kl = 0.f, dec = 0.f, pr = 0.f;
    if (tid < FEAT) {
        int f = tid, g = f / 5, k = f - 5 * g;
        int start = g * 62 + c_off[k], wdt = 2 << k, n2 = wdt >> 1;
        float lognc = c_lognc[k];

        const float2* p2 = reinterpret_cast<const float2*>(sm + start);
        float m = -3.4e38f;
        for (int i = 0; i < n2; i++) {
            float2 v = p2[i];
            m = fmaxf(m, fmaxf(v.x, v.y));
        }
        float s = 0.f;
        for (int i = 0; i < n2; i++) {
            float2 v = p2[i];
            s += __expf(v.x - m) + __expf(v.y - m);
        }
        float lse = m + __logf(s);

        // per-feature q_one_timestep values (only scanner needs them)
        const float la = g_la[t], l1ma = g_l1ma[t];
        float q1w = flae(la,        l1ma - lognc);
        float q1o = flae(CLOG + la, l1ma - lognc);

        // true posterior closed form
        float ev0 = (t == 0) ? 0.f  : flae(lca1,        l1mca1 - lognc);
        float evo = (t == 0) ? CLOG : flae(CLOG + lca1, l1mca1 - lognc);
        float un_oo = evo + q1o;
        float e0, e1, e2, klc, sum_p;
        if (c0 == w) {
            float un_b = ev0 + q1w;
            float mm = fmaxf(un_b, un_oo);
            float ss = __expf(un_b - mm) + (float)(wdt - 1) * __expf(un_oo - mm);
            float l2 = mm + __logf(ss);
            float lt1 = un_b - l2, lt0 = un_oo - l2;
            e0 = __expf(lt0); e1 = __expf(lt1); e2 = e1;
            klc = e1 * lt1 + (float)(wdt - 1) * e0 * lt0;
            sum_p = e1 + (float)(wdt - 1) * e0;
        } else {
            float un_c0 = ev0 + q1o;
            float un_w  = evo + q1w;
            float mm = fmaxf(fmaxf(un_c0, un_w), un_oo);
            float ss = __expf(un_c0 - mm) + __expf(un_w - mm) + (float)(wdt - 2) * __expf(un_oo - mm);
            float l2 = mm + __logf(ss);
            float lt0 = un_oo - l2, lt1 = un_c0 - l2, lt2 = un_w - l2;
            e0 = __expf(lt0); e1 = __expf(lt1); e2 = __expf(lt2);
            klc = e1 * lt1 + e2 * lt2 + (float)(wdt - 2) * e0 * lt0;
            sum_p = e1 + e2 + (float)(wdt - 2) * e0;
        }

        // est-posterior pieces at c0 and w + closed-form lse2
        float Bev = (t == 0) ? 0.f : __expf(l1mca1 - lognc);
        float pc0 = sm[c0], pw = sm[w];
        float smw  = __expf(pw  - lse);
        float smc0 = __expf(pc0 - lse);
        float ev_c0 = (t == 0) ? (pc0 - lse) : __logf(fmaf(smc0, Aev, Bev));
        float ev_w  = (t == 0) ? (pw  - lse) : __logf(fmaf(smw,  Aev, Bev));
        float qwE = __expf(q1w), qoE = __expf(q1o);
        float Z = Aev * fmaf(qwE - qoE, smw, qoE) + Bev * (qwE + (float)(wdt - 1) * qoE);
        float lse2 = __logf(Z);

        // scanner-side KL correction and decoder NLL
        float corr;
        float q1c0;
        if (c0 == w) {
            corr = klc + (lse2 - q1o) * sum_p - (e1 - e0) * ev_c0 - (q1w - q1o) * e1;
            q1c0 = q1w;
        } else {
            corr = klc + (lse2 - q1o) * sum_p - (e1 - e0) * ev_c0 - (e2 - e0) * ev_w
                 - (q1w - q1o) * e2;
            q1c0 = q1o;
        }
        kl  = corr;
        dec = lse2 - ev_c0 - q1c0;

        s_fc[f] = make_float4(lse, e0, Bev, 0.f);
    }
    if (tid < 5) {                              // kl_prior: 5 distinct values x 8 groups
        float lognc = c_lognc[tid];
        float wdt = (float)(2 << tid);
        float lcaT = g_lca[NT - 1], l1mcaT = g_l1mca[NT - 1];
        float lq0 = flae(lcaT,        l1mcaT - lognc);
        float lqo = flae(CLOG + lcaT, l1mcaT - lognc);
        pr = 8.0f * (__expf(lq0) * (lq0 + lognc) + (wdt - 1.0f) * __expf(lqo) * (lqo + lognc));
    }
    __syncthreads();

    // -------- dense accumulation: kl -= e0 * ev_j over all columns --------
    if (act) {
        float4 pv = *reinterpret_cast<const float4*>(sm + j0);
        const float* pp = reinterpret_cast<const float*>(&pv);
        #pragma unroll
        for (int q = 0; q < 4; q++) {
            int f = (fpack >> (8 * q)) & 0xff;
            float4 fc = s_fc[f];
            float lh = pp[q] - fc.x;
            float ev = (t == 0) ? lh : __logf(fmaf(__expf(lh), Aev, fc.z));
            kl -= fc.y * ev;
        }
    }

    float rk = wred(kl), rd = wred(dec), rp = wred(pr);
    int wid = tid >> 5, lane = tid & 31;
    if (lane == 0) { s_red[0][wid] = rk; s_red[1][wid] = rd; s_red[2][wid] = rp; }
    __syncthreads();
    if (tid == 0) {
        float K  = s_red[0][0] + s_red[0][1] + s_red[0][2] + s_red[0][3];
        float Dn = s_red[1][0] + s_red[1][1] + s_red[1][2] + s_red[1][3];
        float P  = s_red[2][0] + s_red[2][1] + s_red[2][2] + s_red[2][3];
        float diff = (t == 0) ? Dn : K;
        g_row_loss[b] = diff * 1000.0f + P;
    }
}

__global__ void reduce_kernel(float* __restrict__ out) {
    __shared__ double sd[32];
    int tid = threadIdx.x;
    double s = 0.0;
    const float4* rl = reinterpret_cast<const float4*>(g_row_loss);
    for (int i = tid; i < BATCH / 4; i += 1024) {
        float4 v = rl[i];
        s += (double)v.x + (double)v.y + (double)v.z + (double)v.w;
    }
    #pragma unroll
    for (int o = 16; o; o >>= 1) s += __shfl_down_sync(0xffffffffu, s, o);
    if ((tid & 31) == 0) sd[tid >> 5] = s;
    __syncthreads();
    if (tid < 32) {
        double v = sd[tid];
        #pragma unroll
        for (int o = 16; o; o >>= 1) v += __shfl_down_sync(0xffffffffu, v, o);
        if (tid == 0) out[0] = (float)(v / (double)BATCH);
    }
}

extern "C" void kernel_launch(void* const* d_in, const int* in_sizes, int n_in,
                              void* d_out, int out_size)
{
    const int*   x0 = nullptr;  const int*   ts = nullptr;
    const float* un = nullptr;  const float* W  = nullptr;
    const float* bi = nullptr;  const float* te = nullptr;
    for (int i = 0; i < n_in; i++) {
        switch (in_sizes[i]) {
            case BATCH * FEAT:   x0 = (const int*)d_in[i];   break;
            case BATCH:          ts = (const int*)d_in[i];   break;
            case BATCH * DCOLS:  un = (const float*)d_in[i]; break;
            case DCOLS * DCOLS:  W  = (const float*)d_in[i]; break;
            case DCOLS:          bi = (const float*)d_in[i]; break;
            case NT * DCOLS:     te = (const float*)d_in[i]; break;
            default: break;
        }
    }
    float* out = (float*)d_out;

    sched_kernel<<<1, 1024>>>();
    dim3 gcs(4, 8);
    cs_part_kernel<<<gcs, 128>>>(W);
    cs_comb_kernel<<<4, 128>>>();
    ddpm_kernel<<<BATCH, 128>>>(x0, ts, un, W, bi, te);
    reduce_kernel<<<1, 1024>>>(out);
}

// round 9
// speedup vs baseline: 1.5977x; 1.1355x over previous
#include <cuda_runtime.h>
#include <cuda_fp16.h>
#include <math.h>

#define BATCH 32768
#define FEAT  40
#define DCOLS 496
#define NT    1000

__device__ float g_la[NT], g_l1ma[NT], g_lca[NT], g_l1mca[NT];
__device__ float g_cs_part[8][DCOLS];
__device__ float g_colsum[DCOLS];
__device__ float g_row_loss[BATCH];
__device__ __align__(16) unsigned short g_Whalf[DCOLS * DCOLS];   // fp16 copy of W

__constant__ float c_lognc[5] = {0.69314718055994531f, 1.38629436111989062f,
                                 2.07944154167983593f, 2.77258872223978124f,
                                 3.46573590279972655f};
__constant__ int c_off[5] = {0, 2, 6, 14, 30};

#define CLOG (-69.07755278982137f)   // log(1e-30)

// fast logaddexp (rel err ~1e-7, budget is 1e-3)
__device__ __forceinline__ float flae(float a, float b) {
    float mx = fmaxf(a, b);
    return mx + __logf(1.0f + __expf(-fabsf(a - b)));
}

__device__ __forceinline__ float wred(float v) {
    #pragma unroll
    for (int o = 16; o; o >>= 1) v += __shfl_down_sync(0xffffffffu, v, o);
    return v;
}

// ---------------------------------------------------------------------------
// Diffusion schedule (float precision is ample at 1e-3 tolerance).
// ---------------------------------------------------------------------------
__global__ void sched_kernel() {
    __shared__ float s[1024];
    int t = threadIdx.x;
    float la = 0.0f;
    if (t < NT) {
        float beta = (t == NT - 1) ? 0.02f : (1e-4f + (float)t * ((0.02f - 1e-4f) / 999.0f));
        la = log1pf(-beta);
        g_la[t]   = la;
        g_l1ma[t] = logf(beta);
    }
    s[t] = la;
    __syncthreads();
    for (int off = 1; off < 1024; off <<= 1) {
        float v = (t >= off) ? s[t - off] : 0.0f;
        __syncthreads();
        s[t] += v;
        __syncthreads();
    }
    if (t < NT) {
        float lc = s[t];
        g_lca[t]   = lc;
        g_l1mca[t] = logf(-expm1f(lc));
    }
}

// ---------------------------------------------------------------------------
// W -> fp16 conversion (halves gather traffic; colsum stays fp32-exact).
// ---------------------------------------------------------------------------
__global__ void wconv_kernel(const float* __restrict__ W) {
    int i = (blockIdx.x * 256 + threadIdx.x) * 4;
    if (i < DCOLS * DCOLS) {
        float4 v = *reinterpret_cast<const float4*>(W + i);
        __half2 h01 = __floats2half2_rn(v.x, v.y);
        __half2 h23 = __floats2half2_rn(v.z, v.w);
        uint2 o;
        o.x = *reinterpret_cast<unsigned int*>(&h01);
        o.y = *reinterpret_cast<unsigned int*>(&h23);
        *reinterpret_cast<uint2*>(reinterpret_cast<char*>(g_Whalf) + (size_t)i * 2) = o;
    }
}

// ---------------------------------------------------------------------------
// colsum[j] = sum_d W[d][j], deterministic two-stage (fp32 W).
// ---------------------------------------------------------------------------
__global__ void cs_part_kernel(const float* __restrict__ W) {
    int j = blockIdx.x * 128 + threadIdx.x;
    int r0 = blockIdx.y * 62;
    if (j < DCOLS) {
        float s0 = 0.f, s1 = 0.f;
        #pragma unroll
        for (int d = 0; d < 62; d += 2) {
            s0 += W[(size_t)(r0 + d) * DCOLS + j];
            s1 += W[(size_t)(r0 + d + 1) * DCOLS + j];
        }
        g_cs_part[blockIdx.y][j] = s0 + s1;
    }
}

__global__ void cs_comb_kernel() {
    int j = blockIdx.x * 128 + threadIdx.x;
    if (j < DCOLS) {
        float s = 0.f;
        #pragma unroll
        for (int i = 0; i < 8; i++) s += g_cs_part[i][j];
        g_colsum[j] = s;
    }
}

// ---------------------------------------------------------------------------
// Main: one block per batch row, 128 threads; thread t owns columns 4t..4t+3.
// ---------------------------------------------------------------------------
__global__ void __launch_bounds__(128, 16) ddpm_kernel(
    const int*   __restrict__ x0,
    const int*   __restrict__ tsteps,
    const float* __restrict__ uni,
    const float* __restrict__ bias,
    const float* __restrict__ temb)
{
    const int b   = blockIdx.x;
    const int tid = threadIdx.x;

    __shared__ __align__(16) float sm[DCOLS];
    __shared__ int    s_col0[FEAT];
    __shared__ int    s_wbyte[FEAT];
    __shared__ float2 s_lp[FEAT];      // {lpo, lp0} q_prior logits
    __shared__ float4 s_fc[FEAT];      // {lse_pred, e0, B, unused} for dense accum
    __shared__ float  s_red[3][4];

    const int   t    = tsteps[b];
    const int   tm1  = (t > 0) ? t - 1 : 0;
    const float lca1 = g_lca[tm1], l1mca1 = g_l1mca[tm1];
    const float Aev  = (t == 0) ? 1.0f : __expf(lca1);     // uniform per block

    // scanner-thread persistent state
    int c0 = 0, w = 0;

    // -------- setup: per-feature q_prior logits + x0 column --------
    if (tid < FEAT) {
        const float lca = g_lca[t], l1mca = g_l1mca[t];
        int f = tid, g = f / 5, k = f - 5 * g;
        int start = g * 62 + c_off[k];
        float lognc = c_lognc[k];
        c0 = start + x0[b * FEAT + f];
        s_col0[f] = c0;
        s_lp[f] = make_float2(flae(CLOG + lca, l1mca - lognc),   // elsewhere
                              flae(lca,        l1mca - lognc));  // at x0 col
    }

    const int  j0  = tid * 4;
    const bool act = (j0 < DCOLS);

    // packed feature ids for this thread's 4 columns
    unsigned int fpack = 0;
    if (act) {
        #pragma unroll
        for (int q = 0; q < 4; q++) {
            int j = j0 + q;
            int g = j / 62, o = j - 62 * g;
            int k = (o < 2) ? 0 : (o < 6) ? 1 : (o < 14) ? 2 : (o < 30) ? 3 : 4;
            fpack |= (unsigned int)(5 * g + k) << (8 * q);
        }
    }
    __syncthreads();

    // -------- phase 1: z = gumbel + q_prior logits --------
    if (act) {
        float4 u4 = *reinterpret_cast<const float4*>(uni + (size_t)b * DCOLS + j0);
        const float* up = reinterpret_cast<const float*>(&u4);
        float4 z; float* zp = reinterpret_cast<float*>(&z);
        #pragma unroll
        for (int q = 0; q < 4; q++) {
            int j = j0 + q;
            int f = (fpack >> (8 * q)) & 0xff;
            float gum = -__logf(-__logf(up[q] + 1e-30f) + 1e-30f);
            float2 lp = s_lp[f];
            zp[q] = gum + ((j == s_col0[f]) ? lp.y : lp.x);
        }
        *reinterpret_cast<float4*>(sm + j0) = z;
    }
    __syncthreads();

    // per-segment argmax (first-max tie break; segment starts even -> float2)
    if (tid < FEAT) {
        int f = tid, g = f / 5, k = f - 5 * g;
        int start = g * 62 + c_off[k], n2 = (2 << k) >> 1;
        const float2* p2 = reinterpret_cast<const float2*>(sm + start);
        float best = -3.4e38f; int bi = 0;
        for (int i = 0; i < n2; i++) {
            float2 v = p2[i];
            if (v.x > best) { best = v.x; bi = 2 * i; }
            if (v.y > best) { best = v.y; bi = 2 * i + 1; }
        }
        w = start + bi;
        s_wbyte[f] = w * (DCOLS * 2);          // byte offset into fp16 W
    }
    __syncthreads();

    // -------- phase 2: gather-sum of 40 fp16 W rows --------
    if (act) {
        float ax = 0.f, ay = 0.f, az = 0.f, aw = 0.f;
        const char* Wb = (const char*)g_Whalf + (size_t)j0 * 2;
        #pragma unroll 8
        for (int f = 0; f < FEAT; f++) {
            uint2 v = *reinterpret_cast<const uint2*>(Wb + s_wbyte[f]);
            float2 f01 = __half22float2(*reinterpret_cast<__half2*>(&v.x));
            float2 f23 = __half22float2(*reinterpret_cast<__half2*>(&v.y));
            ax += f01.x; ay += f01.y; az += f23.x; aw += f23.y;
        }
        float4 cs = *reinterpret_cast<const float4*>(g_colsum + j0);
        float4 bb = *reinterpret_cast<const float4*>(bias + j0);
        float4 te = *reinterpret_cast<const float4*>(temb + (size_t)t * DCOLS + j0);
        float4 pr4;
        pr4.x = CLOG * (cs.x - ax) + bb.x + te.x;
        pr4.y = CLOG * (cs.y - ay) + bb.y + te.y;
        pr4.z = CLOG * (cs.z - az) + bb.z + te.z;
        pr4.w = CLOG * (cs.w - aw) + bb.w + te.w;
        *reinterpret_cast<float4*>(sm + j0) = pr4;
    }
    __syncthreads();

    // -------- scanner: lse(pred), true posterior, closed-form lse2, corrections --
    float kl = 0.f, dec = 0.f, pr = 0.f;
    if (tid < FEAT) {
        int f = tid, g = f / 5, k = f - 5 * g;
        int start = g * 62 + c_off[k], wdt = 2 << k, n2 = wdt >> 1;
        float lognc = c_lognc[k];

        const float2* p2 = reinterpret_cast<const float2*>(sm + start);
        float m = -3.4e38f;
        for (int i = 0; i < n2; i++) {
            float2 v = p2[i];
            m = fmaxf(m, fmaxf(v.x, v.y));
        }
        float s = 0.f;
        for (int i = 0; i < n2; i++) {
            float2 v = p2[i];
            s += __expf(v.x - m) + __expf(v.y - m);
        }
        float lse = m + __logf(s);

        // per-feature q_one_timestep values (only scanner needs them)
        const float la = g_la[t], l1ma = g_l1ma[t];
        float q1w = flae(la,        l1ma - lognc);
        float q1o = flae(CLOG + la, l1ma - lognc);

        // true posterior closed form
        float ev0 = (t == 0) ? 0.f  : flae(lca1,        l1mca1 - lognc);
        float evo = (t == 0) ? CLOG : flae(CLOG + lca1, l1mca1 - lognc);
        float un_oo = evo + q1o;
        float e0, e1, e2, klc, sum_p;
        if (c0 == w) {
            float un_b = ev0 + q1w;
            float mm = fmaxf(un_b, un_oo);
            float ss = __expf(un_b - mm) + (float)(wdt - 1) * __expf(un_oo - mm);
            float l2 = mm + __logf(ss);
            float lt1 = un_b - l2, lt0 = un_oo - l2;
            e0 = __expf(lt0); e1 = __expf(lt1); e2 = e1;
            klc = e1 * lt1 + (float)(wdt - 1) * e0 * lt0;
            sum_p = e1 + (float)(wdt - 1) * e0;
        } else {
            float un_c0 = ev0 + q1o;
            float un_w  = evo + q1w;
            float mm = fmaxf(fmaxf(un_c0, un_w), un_oo);
            float ss = __expf(un_c0 - mm) + __expf(un_w - mm) + (float)(wdt - 2) * __expf(un_oo - mm);
            float l2 = mm + __logf(ss);
            float lt0 = un_oo - l2, lt1 = un_c0 - l2, lt2 = un_w - l2;
            e0 = __expf(lt0); e1 = __expf(lt1); e2 = __expf(lt2);
            klc = e1 * lt1 + e2 * lt2 + (float)(wdt - 2) * e0 * lt0;
            sum_p = e1 + e2 + (float)(wdt - 2) * e0;
        }

        // est-posterior pieces at c0 and w + closed-form lse2
        float Bev = (t == 0) ? 0.f : __expf(l1mca1 - lognc);
        float pc0 = sm[c0], pw = sm[w];
        float smw  = __expf(pw  - lse);
        float smc0 = __expf(pc0 - lse);
        float ev_c0 = (t == 0) ? (pc0 - lse) : __logf(fmaf(smc0, Aev, Bev));
        float ev_w  = (t == 0) ? (pw  - lse) : __logf(fmaf(smw,  Aev, Bev));
        float qwE = __expf(q1w), qoE = __expf(q1o);
        float Z = Aev * fmaf(qwE - qoE, smw, qoE) + Bev * (qwE + (float)(wdt - 1) * qoE);
        float lse2 = __logf(Z);

        // scanner-side KL correction and decoder NLL
        float corr;
        float q1c0;
        if (c0 == w) {
            corr = klc + (lse2 - q1o) * sum_p - (e1 - e0) * ev_c0 - (q1w - q1o) * e1;
            q1c0 = q1w;
        } else {
            corr = klc + (lse2 - q1o) * sum_p - (e1 - e0) * ev_c0 - (e2 - e0) * ev_w
                 - (q1w - q1o) * e2;
            q1c0 = q1o;
        }
        kl  = corr;
        dec = lse2 - ev_c0 - q1c0;

        s_fc[f] = make_float4(lse, e0, Bev, 0.f);
    }
    if (tid < 5) {                              // kl_prior: 5 distinct values x 8 groups
        float lognc = c_lognc[tid];
        float wdt = (float)(2 << tid);
        float lcaT = g_lca[NT - 1], l1mcaT = g_l1mca[NT - 1];
        float lq0 = flae(lcaT,        l1mcaT - lognc);
        float lqo = flae(CLOG + lcaT, l1mcaT - lognc);
        pr = 8.0f * (__expf(lq0) * (lq0 + lognc) + (wdt - 1.0f) * __expf(lqo) * (lqo + lognc));
    }
    __syncthreads();

    // -------- dense accumulation: kl -= e0 * ev_j over all columns --------
    if (act) {
        float4 pv = *reinterpret_cast<const float4*>(sm + j0);
        const float* pp = reinterpret_cast<const float*>(&pv);
        #pragma unroll
        for (int q = 0; q < 4; q++) {
            int f = (fpack >> (8 * q)) & 0xff;
            float4 fc = s_fc[f];
            float lh = pp[q] - fc.x;
            float ev = (t == 0) ? lh : __logf(fmaf(__expf(lh), Aev, fc.z));
            kl -= fc.y * ev;
        }
    }

    float rk = wred(kl), rd = wred(dec), rp = wred(pr);
    int wid = tid >> 5, lane = tid & 31;
    if (lane == 0) { s_red[0][wid] = rk; s_red[1][wid] = rd; s_red[2][wid] = rp; }
    __syncthreads();
    if (tid == 0) {
        float K  = s_red[0][0] + s_red[0][1] + s_red[0][2] + s_red[0][3];
        float Dn = s_red[1][0] + s_red[1][1] + s_red[1][2] + s_red[1][3];
        float P  = s_red[2][0] + s_red[2][1] + s_red[2][2] + s_red[2][3];
        float diff = (t == 0) ? Dn : K;
        g_row_loss[b] = diff * 1000.0f + P;
    }
}

__global__ void reduce_kernel(float* __restrict__ out) {
    __shared__ double sd[32];
    int tid = threadIdx.x;
    double s = 0.0;
    const float4* rl = reinterpret_cast<const float4*>(g_row_loss);
    for (int i = tid; i < BATCH / 4; i += 1024) {
        float4 v = rl[i];
        s += (double)v.x + (double)v.y + (double)v.z + (double)v.w;
    }
    #pragma unroll
    for (int o = 16; o; o >>= 1) s += __shfl_down_sync(0xffffffffu, s, o);
    if ((tid & 31) == 0) sd[tid >> 5] = s;
    __syncthreads();
    if (tid < 32) {
        double v = sd[tid];
        #pragma unroll
        for (int o = 16; o; o >>= 1) v += __shfl_down_sync(0xffffffffu, v, o);
        if (tid == 0) out[0] = (float)(v / (double)BATCH);
    }
}

extern "C" void kernel_launch(void* const* d_in, const int* in_sizes, int n_in,
                              void* d_out, int out_size)
{
    const int*   x0 = nullptr;  const int*   ts = nullptr;
    const float* un = nullptr;  const float* W  = nullptr;
    const float* bi = nullptr;  const float* te = nullptr;
    for (int i = 0; i < n_in; i++) {
        switch (in_sizes[i]) {
            case BATCH * FEAT:   x0 = (const int*)d_in[i];   break;
            case BATCH:          ts = (const int*)d_in[i];   break;
            case BATCH * DCOLS:  un = (const float*)d_in[i]; break;
            case DCOLS * DCOLS:  W  = (const float*)d_in[i]; break;
            case DCOLS:          bi = (const float*)d_in[i]; break;
            case NT * DCOLS:     te = (const float*)d_in[i]; break;
            default: break;
        }
    }
    float* out = (float*)d_out;

    sched_kernel<<<1, 1024>>>();
    wconv_kernel<<<(DCOLS * DCOLS / 4 + 255) / 256, 256>>>(W);
    dim3 gcs(4, 8);
    cs_part_kernel<<<gcs, 128>>>(W);
    cs_comb_kernel<<<4, 128>>>();
    ddpm_kernel<<<BATCH, 128>>>(x0, ts, un, bi, te);
    reduce_kernel<<<1, 1024>>>(out);
}